// round 4
// baseline (speedup 1.0000x reference)
#include <cuda_runtime.h>
#include <cuda_bf16.h>

#define NB 256   // batch
#define NC 256   // columns
#define NP 256   // prompts
#define ND 256   // dim
#define LN_EPS 1e-5f

// ---------------- scratch (device globals; no runtime allocation) ----------
__device__ float g_xcol[NC * ND];            // LN(emb_column)          [C,D]
__device__ float g_xprompt[NP * ND];         // prompt features         [P,D]
__device__ float g_mask[NP * NC];            // softmax mask            [P,C]
__device__ float g_xemb[NB * NC * ND];       // LN(relu(...)) 64 MiB    [B,C,D]

// ---------------- helpers ---------------------------------------------------
__device__ __forceinline__ void block_reduce_sum2(float* r1, float* r2,
                                                  float a, float b, int t,
                                                  float* o1, float* o2) {
    __syncthreads();
    r1[t] = a; r2[t] = b;
    __syncthreads();
    #pragma unroll
    for (int s = 128; s > 0; s >>= 1) {
        if (t < s) { r1[t] += r1[t + s]; r2[t] += r2[t + s]; }
        __syncthreads();
    }
    *o1 = r1[0]; *o2 = r2[0];
}

// ---------------- K1: x_col = LN(emb_column) --------------------------------
__global__ void __launch_bounds__(256)
k_ln_col(const float* __restrict__ emb_col,
         const float* __restrict__ w, const float* __restrict__ b) {
    __shared__ float r1[256], r2[256];
    int c = blockIdx.x, t = threadIdx.x;
    float v = emb_col[c * ND + t];
    float s, sq;
    block_reduce_sum2(r1, r2, v, v * v, t, &s, &sq);
    float mu = s * (1.0f / ND);
    float var = sq * (1.0f / ND) - mu * mu;
    float rs = rsqrtf(var + LN_EPS);
    g_xcol[c * ND + t] = (v - mu) * rs * w[t] + b[t];
}

// ---------------- K2: x_prompt = [LN(emb_prompt)|prev] @ W^T + b + emb_prompt
// 64 blocks, 4 prompt rows per block, 256 threads (thread = output dim d)
__global__ void __launch_bounds__(256)
k_prompt(const float* __restrict__ emb_prompt,
         const float* __restrict__ prev,
         const float* __restrict__ lnw, const float* __restrict__ lnb,
         const float* __restrict__ W,   // [D, 2D] row-major
         const float* __restrict__ dbias) {
    __shared__ float r1[256], r2[256];
    __shared__ float s_in[4][2 * ND];      // 8 KB
    __shared__ float Ws[256][17];          // [d][k] padded, 17.4 KB
    int t = threadIdx.x;
    int p0 = blockIdx.x * 4;

    // build inputs: LN(emb_prompt[p]) || prev[p]
    #pragma unroll
    for (int j = 0; j < 4; ++j) {
        int p = p0 + j;
        float v = emb_prompt[p * ND + t];
        float s, sq;
        block_reduce_sum2(r1, r2, v, v * v, t, &s, &sq);
        float mu = s * (1.0f / ND);
        float rs = rsqrtf(sq * (1.0f / ND) - mu * mu + LN_EPS);
        s_in[j][t]      = (v - mu) * rs * lnw[t] + lnb[t];
        s_in[j][ND + t] = prev[p * ND + t];
    }
    __syncthreads();

    float acc[4] = {0.f, 0.f, 0.f, 0.f};
    for (int kc = 0; kc < 2 * ND; kc += 16) {
        // stage W[:, kc:kc+16] coalesced along k
        #pragma unroll
        for (int i = 0; i < 16; ++i) {
            int idx = i * 256 + t;
            int k = idx & 15, d = idx >> 4;
            Ws[d][k] = W[d * (2 * ND) + kc + k];
        }
        __syncthreads();
        #pragma unroll
        for (int k = 0; k < 16; ++k) {
            float wv = Ws[t][k];
            #pragma unroll
            for (int j = 0; j < 4; ++j)
                acc[j] += s_in[j][kc + k] * wv;
        }
        __syncthreads();
    }
    #pragma unroll
    for (int j = 0; j < 4; ++j) {
        int p = p0 + j;
        g_xprompt[p * ND + t] = acc[j] + dbias[t] + emb_prompt[p * ND + t];
    }
}

// ---------------- K3: mask = softmax(x_prompt @ x_col^T) --------------------
// 64 blocks, 4 prompt rows each, thread = column c
__global__ void __launch_bounds__(256)
k_mask() {
    __shared__ float r1[256];
    __shared__ float s_xp[4][ND];          // 4 KB
    __shared__ float xcs[256][17];         // 17.4 KB
    int t = threadIdx.x;
    int p0 = blockIdx.x * 4;
    #pragma unroll
    for (int j = 0; j < 4; ++j)
        s_xp[j][t] = g_xprompt[(p0 + j) * ND + t];
    __syncthreads();

    float acc[4] = {0.f, 0.f, 0.f, 0.f};
    for (int dc = 0; dc < ND; dc += 16) {
        #pragma unroll
        for (int i = 0; i < 16; ++i) {
            int idx = i * 256 + t;
            int k = idx & 15, c = idx >> 4;
            xcs[c][k] = g_xcol[c * ND + dc + k];
        }
        __syncthreads();
        #pragma unroll
        for (int k = 0; k < 16; ++k) {
            float xv = xcs[t][k];
            #pragma unroll
            for (int j = 0; j < 4; ++j)
                acc[j] += s_xp[j][dc + k] * xv;
        }
        __syncthreads();
    }
    // softmax over c (= thread dim) per row
    #pragma unroll
    for (int j = 0; j < 4; ++j) {
        __syncthreads();
        r1[t] = acc[j];
        __syncthreads();
        #pragma unroll
        for (int s = 128; s > 0; s >>= 1) {
            if (t < s) r1[t] = fmaxf(r1[t], r1[t + s]);
            __syncthreads();
        }
        float m = r1[0];
        float e = expf(acc[j] - m);
        __syncthreads();
        r1[t] = e;
        __syncthreads();
        #pragma unroll
        for (int s = 128; s > 0; s >>= 1) {
            if (t < s) r1[t] += r1[t + s];
            __syncthreads();
        }
        g_mask[(p0 + j) * NC + t] = e / r1[0];
    }
}

// ---------------- K4: x_emb = LN(relu(fbias + x*fw)) ------------------------
// grid (32, 256): blockIdx.y = b, 8 warps, warp = one c-row, warp-level LN
__global__ void __launch_bounds__(256)
k_xemb(const float* __restrict__ x,
       const float* __restrict__ fw, const float* __restrict__ fb,
       const float* __restrict__ lnw, const float* __restrict__ lnb) {
    int t = threadIdx.x;
    int lane = t & 31;
    int b = blockIdx.y;
    int c = blockIdx.x * 8 + (t >> 5);
    float xs = x[b * NC + c];
    float r[8], sum = 0.f, sq = 0.f;
    #pragma unroll
    for (int i = 0; i < 8; ++i) {
        int d = i * 32 + lane;
        float v = fb[c * ND + d] + xs * fw[c * ND + d];
        v = fmaxf(v, 0.f);
        r[i] = v; sum += v; sq += v * v;
    }
    #pragma unroll
    for (int off = 16; off > 0; off >>= 1) {
        sum += __shfl_xor_sync(0xffffffffu, sum, off);
        sq  += __shfl_xor_sync(0xffffffffu, sq, off);
    }
    float mu = sum * (1.0f / ND);
    float rs = rsqrtf(sq * (1.0f / ND) - mu * mu + LN_EPS);
    float* out = g_xemb + ((size_t)b * NC + c) * ND;
    #pragma unroll
    for (int i = 0; i < 8; ++i) {
        int d = i * 32 + lane;
        out[d] = (r[i] - mu) * rs * lnw[d] + lnb[d];
    }
}

// ---------------- K5: batched GEMM out[b] = mask @ x_emb[b] + epilogue ------
// grid (2,2,256), 256 threads, 128x128 tile, 8x8 per thread, BK=8, dbl-buffer
__global__ void __launch_bounds__(256)
k_out_gemm(float* __restrict__ out,
           const float* __restrict__ ew,    // expand_weight [P,1]
           const float* __restrict__ eb) {  // expand_bias   [P]
    __shared__ float As[2][8][128];
    __shared__ float Bs[2][8][128];
    const int b  = blockIdx.z;
    const int p0 = blockIdx.y * 128, d0 = blockIdx.x * 128;
    const int t  = threadIdx.x;
    const int tx = t & 15, ty = t >> 4;
    const float* A  = g_mask;                         // [P][C]
    const float* Bm = g_xemb + (size_t)b * NC * ND;   // [C][D]

    const int a_row = t >> 1,  a_col = (t & 1) * 4;   // A tile [128][8]
    const int b_row = t >> 5,  b_col = (t & 31) * 4;  // B tile [8][128]

    float acc[8][8];
    #pragma unroll
    for (int i = 0; i < 8; ++i)
        #pragma unroll
        for (int j = 0; j < 8; ++j) acc[i][j] = 0.f;

    float4 av = *(const float4*)&A[(p0 + a_row) * NC + a_col];
    float4 bv = *(const float4*)&Bm[b_row * ND + d0 + b_col];
    As[0][a_col + 0][a_row] = av.x; As[0][a_col + 1][a_row] = av.y;
    As[0][a_col + 2][a_row] = av.z; As[0][a_col + 3][a_row] = av.w;
    *(float4*)&Bs[0][b_row][b_col] = bv;
    __syncthreads();

    for (int kt = 0; kt < 32; ++kt) {
        int cur = kt & 1;
        if (kt < 31) {
            int kn = (kt + 1) * 8;
            av = *(const float4*)&A[(p0 + a_row) * NC + kn + a_col];
            bv = *(const float4*)&Bm[(kn + b_row) * ND + d0 + b_col];
        }
        #pragma unroll
        for (int k = 0; k < 8; ++k) {
            float4 a0 = *(float4*)&As[cur][k][ty * 8];
            float4 a1 = *(float4*)&As[cur][k][ty * 8 + 4];
            float4 b0 = *(float4*)&Bs[cur][k][tx * 8];
            float4 b1 = *(float4*)&Bs[cur][k][tx * 8 + 4];
            float ar[8] = {a0.x, a0.y, a0.z, a0.w, a1.x, a1.y, a1.z, a1.w};
            float br[8] = {b0.x, b0.y, b0.z, b0.w, b1.x, b1.y, b1.z, b1.w};
            #pragma unroll
            for (int i = 0; i < 8; ++i)
                #pragma unroll
                for (int j = 0; j < 8; ++j)
                    acc[i][j] += ar[i] * br[j];
        }
        if (kt < 31) {
            int nxt = cur ^ 1;
            As[nxt][a_col + 0][a_row] = av.x; As[nxt][a_col + 1][a_row] = av.y;
            As[nxt][a_col + 2][a_row] = av.z; As[nxt][a_col + 3][a_row] = av.w;
            *(float4*)&Bs[nxt][b_row][b_col] = bv;
        }
        __syncthreads();
    }

    // epilogue: out[0,b,p,d] = acc*(1+ew[p]) + mask[b,p]*eb[b]
    float ebb = eb[b];
    #pragma unroll
    for (int i = 0; i < 8; ++i) {
        int p = p0 + ty * 8 + i;
        float sc = 1.0f + ew[p];
        float bt = g_mask[b * NC + p] * ebb;
        size_t base = ((size_t)(b * NP + p)) * ND + d0 + tx * 8;
        #pragma unroll
        for (int j = 0; j < 8; j += 4) {
            float4 v;
            v.x = acc[i][j + 0] * sc + bt;
            v.y = acc[i][j + 1] * sc + bt;
            v.z = acc[i][j + 2] * sc + bt;
            v.w = acc[i][j + 3] * sc + bt;
            *(float4*)&out[base + j] = v;
        }
    }
}

// ---------------- launch -----------------------------------------------------
extern "C" void kernel_launch(void* const* d_in, const int* in_sizes, int n_in,
                              void* d_out, int out_size) {
    const float* x      = (const float*)d_in[0];   // [B,C]
    const float* prev   = (const float*)d_in[1];   // [P,D]
    const float* fw     = (const float*)d_in[2];   // [C,D]
    const float* fb     = (const float*)d_in[3];   // [1,C,D]
    const float* lnew   = (const float*)d_in[4];
    const float* lneb   = (const float*)d_in[5];
    const float* lncw   = (const float*)d_in[6];
    const float* lncb   = (const float*)d_in[7];
    const float* lnpw   = (const float*)d_in[8];
    const float* lnpb   = (const float*)d_in[9];
    const float* W      = (const float*)d_in[10];  // [D,2D]
    const float* db     = (const float*)d_in[11];  // [D]
    const float* embc   = (const float*)d_in[12];  // [C,D]
    const float* embp   = (const float*)d_in[13];  // [P,D]
    const float* ew     = (const float*)d_in[14];  // [P,1]
    const float* eb     = (const float*)d_in[15];  // [P]
    float* out = (float*)d_out;

    k_ln_col<<<NC, 256>>>(embc, lncw, lncb);
    k_prompt<<<NP / 4, 256>>>(embp, prev, lnpw, lnpb, W, db);
    k_mask<<<NP / 4, 256>>>();
    k_xemb<<<dim3(NC / 8, NB), 256>>>(x, fw, fb, lnew, lneb);
    k_out_gemm<<<dim3(2, 2, NB), 256>>>(out, ew, eb);
}

// round 5
// speedup vs baseline: 2.9080x; 2.9080x over previous
#include <cuda_runtime.h>
#include <cuda_bf16.h>

#define NB 256   // batch
#define NC 256   // columns
#define NP 256   // prompts
#define ND 256   // dim
#define LN_EPS 1e-5f

// ---------------- scratch (device globals; no runtime allocation) ----------
__device__ float g_xcol[NC * ND];            // LN(emb_column)          [C,D]
__device__ float g_xprompt[NP * ND];         // prompt features         [P,D]
__device__ float g_mask[NP * NC];            // softmax mask            [P,C]
__device__ float g_xemb[NB * NC * ND];       // LN(relu(...)) 64 MiB    [B,C,D]

// ---------------- helpers ---------------------------------------------------
__device__ __forceinline__ void block_reduce_sum2(float* r1, float* r2,
                                                  float a, float b, int t,
                                                  float* o1, float* o2) {
    __syncthreads();
    r1[t] = a; r2[t] = b;
    __syncthreads();
    #pragma unroll
    for (int s = 128; s > 0; s >>= 1) {
        if (t < s) { r1[t] += r1[t + s]; r2[t] += r2[t + s]; }
        __syncthreads();
    }
    *o1 = r1[0]; *o2 = r2[0];
}

__device__ __forceinline__ unsigned f2tf32(float f) {
    unsigned r;
    asm("cvt.rna.tf32.f32 %0, %1;" : "=r"(r) : "f"(f));
    return r;
}

__device__ __forceinline__ void mma_tf32(float& c0, float& c1, float& c2, float& c3,
                                         unsigned a0, unsigned a1, unsigned a2, unsigned a3,
                                         unsigned b0, unsigned b1) {
    asm volatile(
        "mma.sync.aligned.m16n8k8.row.col.f32.tf32.tf32.f32 "
        "{%0,%1,%2,%3}, {%4,%5,%6,%7}, {%8,%9}, {%0,%1,%2,%3};"
        : "+f"(c0), "+f"(c1), "+f"(c2), "+f"(c3)
        : "r"(a0), "r"(a1), "r"(a2), "r"(a3), "r"(b0), "r"(b1));
}

// ---------------- K1: x_col = LN(emb_column) --------------------------------
__global__ void __launch_bounds__(256)
k_ln_col(const float* __restrict__ emb_col,
         const float* __restrict__ w, const float* __restrict__ b) {
    __shared__ float r1[256], r2[256];
    int c = blockIdx.x, t = threadIdx.x;
    float v = emb_col[c * ND + t];
    float s, sq;
    block_reduce_sum2(r1, r2, v, v * v, t, &s, &sq);
    float mu = s * (1.0f / ND);
    float var = sq * (1.0f / ND) - mu * mu;
    float rs = rsqrtf(var + LN_EPS);
    g_xcol[c * ND + t] = (v - mu) * rs * w[t] + b[t];
}

// ---------------- K2: x_prompt = [LN(emb_prompt)|prev] @ W^T + b + emb_prompt
__global__ void __launch_bounds__(256)
k_prompt(const float* __restrict__ emb_prompt,
         const float* __restrict__ prev,
         const float* __restrict__ lnw, const float* __restrict__ lnb,
         const float* __restrict__ W,   // [D, 2D] row-major
         const float* __restrict__ dbias) {
    __shared__ float r1[256], r2[256];
    __shared__ float s_in[4][2 * ND];
    __shared__ float Ws[256][17];
    int t = threadIdx.x;
    int p0 = blockIdx.x * 4;

    #pragma unroll
    for (int j = 0; j < 4; ++j) {
        int p = p0 + j;
        float v = emb_prompt[p * ND + t];
        float s, sq;
        block_reduce_sum2(r1, r2, v, v * v, t, &s, &sq);
        float mu = s * (1.0f / ND);
        float rs = rsqrtf(sq * (1.0f / ND) - mu * mu + LN_EPS);
        s_in[j][t]      = (v - mu) * rs * lnw[t] + lnb[t];
        s_in[j][ND + t] = prev[p * ND + t];
    }
    __syncthreads();

    float acc[4] = {0.f, 0.f, 0.f, 0.f};
    for (int kc = 0; kc < 2 * ND; kc += 16) {
        #pragma unroll
        for (int i = 0; i < 16; ++i) {
            int idx = i * 256 + t;
            int k = idx & 15, d = idx >> 4;
            Ws[d][k] = W[d * (2 * ND) + kc + k];
        }
        __syncthreads();
        #pragma unroll
        for (int k = 0; k < 16; ++k) {
            float wv = Ws[t][k];
            #pragma unroll
            for (int j = 0; j < 4; ++j)
                acc[j] += s_in[j][kc + k] * wv;
        }
        __syncthreads();
    }
    #pragma unroll
    for (int j = 0; j < 4; ++j) {
        int p = p0 + j;
        g_xprompt[p * ND + t] = acc[j] + dbias[t] + emb_prompt[p * ND + t];
    }
}

// ---------------- K3: mask = softmax(x_prompt @ x_col^T) --------------------
__global__ void __launch_bounds__(256)
k_mask() {
    __shared__ float r1[256];
    __shared__ float s_xp[4][ND];
    __shared__ float xcs[256][17];
    int t = threadIdx.x;
    int p0 = blockIdx.x * 4;
    #pragma unroll
    for (int j = 0; j < 4; ++j)
        s_xp[j][t] = g_xprompt[(p0 + j) * ND + t];
    __syncthreads();

    float acc[4] = {0.f, 0.f, 0.f, 0.f};
    for (int dc = 0; dc < ND; dc += 16) {
        #pragma unroll
        for (int i = 0; i < 16; ++i) {
            int idx = i * 256 + t;
            int k = idx & 15, c = idx >> 4;
            xcs[c][k] = g_xcol[c * ND + dc + k];
        }
        __syncthreads();
        #pragma unroll
        for (int k = 0; k < 16; ++k) {
            float xv = xcs[t][k];
            #pragma unroll
            for (int j = 0; j < 4; ++j)
                acc[j] += s_xp[j][dc + k] * xv;
        }
        __syncthreads();
    }
    #pragma unroll
    for (int j = 0; j < 4; ++j) {
        __syncthreads();
        r1[t] = acc[j];
        __syncthreads();
        #pragma unroll
        for (int s = 128; s > 0; s >>= 1) {
            if (t < s) r1[t] = fmaxf(r1[t], r1[t + s]);
            __syncthreads();
        }
        float m = r1[0];
        float e = expf(acc[j] - m);
        __syncthreads();
        r1[t] = e;
        __syncthreads();
        #pragma unroll
        for (int s = 128; s > 0; s >>= 1) {
            if (t < s) r1[t] += r1[t + s];
            __syncthreads();
        }
        g_mask[(p0 + j) * NC + t] = e / r1[0];
    }
}

// ---------------- K4: x_emb = LN(relu(fbias + x*fw)) ------------------------
__global__ void __launch_bounds__(256)
k_xemb(const float* __restrict__ x,
       const float* __restrict__ fw, const float* __restrict__ fb,
       const float* __restrict__ lnw, const float* __restrict__ lnb) {
    int t = threadIdx.x;
    int lane = t & 31;
    int b = blockIdx.y;
    int c = blockIdx.x * 8 + (t >> 5);
    float xs = x[b * NC + c];
    float r[8], sum = 0.f, sq = 0.f;
    #pragma unroll
    for (int i = 0; i < 8; ++i) {
        int d = i * 32 + lane;
        float v = fb[c * ND + d] + xs * fw[c * ND + d];
        v = fmaxf(v, 0.f);
        r[i] = v; sum += v; sq += v * v;
    }
    #pragma unroll
    for (int off = 16; off > 0; off >>= 1) {
        sum += __shfl_xor_sync(0xffffffffu, sum, off);
        sq  += __shfl_xor_sync(0xffffffffu, sq, off);
    }
    float mu = sum * (1.0f / ND);
    float rs = rsqrtf(sq * (1.0f / ND) - mu * mu + LN_EPS);
    float* out = g_xemb + ((size_t)b * NC + c) * ND;
    #pragma unroll
    for (int i = 0; i < 8; ++i) {
        int d = i * 32 + lane;
        out[d] = (r[i] - mu) * rs * lnw[d] + lnb[d];
    }
}

// ---------------- K5: batched tf32 tensor-core GEMM -------------------------
// out[0,b,p,d] = (1+ew[p]) * sum_c mask[p,c]*xemb[b,c,d] + mask[b,p]*eb[b]
// grid (D/128, P/128, B) = (2,2,256); 256 thr = 8 warps (2m x 4n), warp 64x32.
// BK=16, double-buffered smem. Padded strides: A=20, B=136 -> conflict-free
// fragment LDS (A: bank=(20g+tg)%32 unique; B: bank=(8tg+g)%32 unique).
#define ASTR 20
#define BSTR 136
__global__ void __launch_bounds__(256)
k_out_mma(float* __restrict__ out,
          const float* __restrict__ ew,    // expand_weight [P,1]
          const float* __restrict__ eb) {  // expand_bias   [P]
    __shared__ unsigned As[2][128 * ASTR];   // [row][k] tf32
    __shared__ unsigned Bs[2][16 * BSTR];    // [k][col] tf32

    const int b  = blockIdx.z;
    const int p0 = blockIdx.y * 128, d0 = blockIdx.x * 128;
    const int t  = threadIdx.x;
    const int lane = t & 31;
    const int g  = lane >> 2;       // groupID (0..7)
    const int tg = lane & 3;        // thread-in-group
    const int warp = t >> 5;
    const int wm = warp & 1;        // 0..1 -> 64-row slab
    const int wn = warp >> 1;       // 0..3 -> 32-col slab

    const float* A  = g_mask;                          // [P][C]
    const float* Bm = g_xemb + (size_t)b * NC * ND;    // [C][D]

    // global-load assignments
    const int a_row = t >> 1, a_c = (t & 1) * 8;       // A: 128 x 16 tile
    const int b_row = t >> 4, b_c = (t & 15) * 8;      // B: 16 x 128 tile

    float acc[4][4][4];
    #pragma unroll
    for (int i = 0; i < 4; ++i)
        #pragma unroll
        for (int j = 0; j < 4; ++j)
            #pragma unroll
            for (int k = 0; k < 4; ++k) acc[i][j][k] = 0.f;

    // ---- preload tile 0
    float4 av0 = *(const float4*)&A[(p0 + a_row) * NC + a_c];
    float4 av1 = *(const float4*)&A[(p0 + a_row) * NC + a_c + 4];
    float4 bv0 = *(const float4*)&Bm[b_row * ND + d0 + b_c];
    float4 bv1 = *(const float4*)&Bm[b_row * ND + d0 + b_c + 4];
    {
        unsigned* ap = &As[0][a_row * ASTR + a_c];
        ap[0] = f2tf32(av0.x); ap[1] = f2tf32(av0.y);
        ap[2] = f2tf32(av0.z); ap[3] = f2tf32(av0.w);
        ap[4] = f2tf32(av1.x); ap[5] = f2tf32(av1.y);
        ap[6] = f2tf32(av1.z); ap[7] = f2tf32(av1.w);
        unsigned* bp = &Bs[0][b_row * BSTR + b_c];
        bp[0] = f2tf32(bv0.x); bp[1] = f2tf32(bv0.y);
        bp[2] = f2tf32(bv0.z); bp[3] = f2tf32(bv0.w);
        bp[4] = f2tf32(bv1.x); bp[5] = f2tf32(bv1.y);
        bp[6] = f2tf32(bv1.z); bp[7] = f2tf32(bv1.w);
    }
    __syncthreads();

    for (int kt = 0; kt < 16; ++kt) {
        const int cur = kt & 1;
        if (kt < 15) {
            int kn = (kt + 1) * 16;
            av0 = *(const float4*)&A[(p0 + a_row) * NC + kn + a_c];
            av1 = *(const float4*)&A[(p0 + a_row) * NC + kn + a_c + 4];
            bv0 = *(const float4*)&Bm[(kn + b_row) * ND + d0 + b_c];
            bv1 = *(const float4*)&Bm[(kn + b_row) * ND + d0 + b_c + 4];
        }
        #pragma unroll
        for (int s = 0; s < 2; ++s) {
            const int ko = s * 8;
            // A fragments: 4 m-frags x 4 regs
            unsigned af[4][4];
            #pragma unroll
            for (int mf = 0; mf < 4; ++mf) {
                int r0 = wm * 64 + mf * 16 + g;
                af[mf][0] = As[cur][r0 * ASTR + ko + tg];
                af[mf][1] = As[cur][(r0 + 8) * ASTR + ko + tg];
                af[mf][2] = As[cur][r0 * ASTR + ko + tg + 4];
                af[mf][3] = As[cur][(r0 + 8) * ASTR + ko + tg + 4];
            }
            #pragma unroll
            for (int nf = 0; nf < 4; ++nf) {
                int cb = wn * 32 + nf * 8 + g;
                unsigned b0 = Bs[cur][(ko + tg) * BSTR + cb];
                unsigned b1 = Bs[cur][(ko + tg + 4) * BSTR + cb];
                #pragma unroll
                for (int mf = 0; mf < 4; ++mf)
                    mma_tf32(acc[mf][nf][0], acc[mf][nf][1],
                             acc[mf][nf][2], acc[mf][nf][3],
                             af[mf][0], af[mf][1], af[mf][2], af[mf][3],
                             b0, b1);
            }
        }
        if (kt < 15) {
            const int nxt = cur ^ 1;
            unsigned* ap = &As[nxt][a_row * ASTR + a_c];
            ap[0] = f2tf32(av0.x); ap[1] = f2tf32(av0.y);
            ap[2] = f2tf32(av0.z); ap[3] = f2tf32(av0.w);
            ap[4] = f2tf32(av1.x); ap[5] = f2tf32(av1.y);
            ap[6] = f2tf32(av1.z); ap[7] = f2tf32(av1.w);
            unsigned* bp = &Bs[nxt][b_row * BSTR + b_c];
            bp[0] = f2tf32(bv0.x); bp[1] = f2tf32(bv0.y);
            bp[2] = f2tf32(bv0.z); bp[3] = f2tf32(bv0.w);
            bp[4] = f2tf32(bv1.x); bp[5] = f2tf32(bv1.y);
            bp[6] = f2tf32(bv1.z); bp[7] = f2tf32(bv1.w);
        }
        __syncthreads();
    }

    // ---- epilogue: scale + bias, fp32
    const float ebb = eb[b];
    #pragma unroll
    for (int mf = 0; mf < 4; ++mf) {
        int pA = p0 + wm * 64 + mf * 16 + g;       // rows for c0,c1
        int pB = pA + 8;                           // rows for c2,c3
        float scA = 1.0f + ew[pA];
        float scB = 1.0f + ew[pB];
        float btA = g_mask[b * NC + pA] * ebb;
        float btB = g_mask[b * NC + pB] * ebb;
        #pragma unroll
        for (int nf = 0; nf < 4; ++nf) {
            int d = d0 + wn * 32 + nf * 8 + 2 * tg;
            float2 vA, vB;
            vA.x = acc[mf][nf][0] * scA + btA;
            vA.y = acc[mf][nf][1] * scA + btA;
            vB.x = acc[mf][nf][2] * scB + btB;
            vB.y = acc[mf][nf][3] * scB + btB;
            *(float2*)&out[((size_t)(b * NP + pA)) * ND + d] = vA;
            *(float2*)&out[((size_t)(b * NP + pB)) * ND + d] = vB;
        }
    }
}

// ---------------- launch -----------------------------------------------------
extern "C" void kernel_launch(void* const* d_in, const int* in_sizes, int n_in,
                              void* d_out, int out_size) {
    const float* x      = (const float*)d_in[0];   // [B,C]
    const float* prev   = (const float*)d_in[1];   // [P,D]
    const float* fw     = (const float*)d_in[2];   // [C,D]
    const float* fb     = (const float*)d_in[3];   // [1,C,D]
    const float* lnew   = (const float*)d_in[4];
    const float* lneb   = (const float*)d_in[5];
    const float* lncw   = (const float*)d_in[6];
    const float* lncb   = (const float*)d_in[7];
    const float* lnpw   = (const float*)d_in[8];
    const float* lnpb   = (const float*)d_in[9];
    const float* W      = (const float*)d_in[10];  // [D,2D]
    const float* db     = (const float*)d_in[11];  // [D]
    const float* embc   = (const float*)d_in[12];  // [C,D]
    const float* embp   = (const float*)d_in[13];  // [P,D]
    const float* ew     = (const float*)d_in[14];  // [P,1]
    const float* eb     = (const float*)d_in[15];  // [P]
    float* out = (float*)d_out;

    k_ln_col<<<NC, 256>>>(embc, lncw, lncb);
    k_prompt<<<NP / 4, 256>>>(embp, prev, lnpw, lnpb, W, db);
    k_mask<<<NP / 4, 256>>>();
    k_xemb<<<dim3(NC / 8, NB), 256>>>(x, fw, fb, lnew, lneb);
    k_out_mma<<<dim3(2, 2, NB), 256>>>(out, ew, eb);
}